// round 16
// baseline (speedup 1.0000x reference)
#include <cuda_runtime.h>
#include <cuda_bf16.h>
#include <stdint.h>

// Problem constants (fixed by dataset)
#define DN 50000     // nodes
#define DE 600000    // edges
#define DD 128       // feature dim
#define DR 8         // relations
#define NR (DR * DN) // 400000 (rel,dst) segments, rel-major
#define NCHUNK 9     // root + 8 relations
#define FULLM 0xffffffffu
#define SB   131     // scan blocks (co-resident, spin-safe)
#define SPAN 3072
#define CHF  (DD * DD)   // 16384 floats per chunk tile

// ---------------- scratch (device globals; no allocs allowed) ----------------
__device__ int   g_cnt[NR];
__device__ int   g_rowptr2[NR + 1];
__device__ int   g_woff[NR];
__device__ int   g_scan_agg[SB];
__device__ int   g_scan_pfx[SB];
__device__ int   g_scan_flag[SB];
__device__ int2  g_emeta[DE];            // .x = src | (dst<<16), .y = unused
__device__ float g_h[(size_t)DN * DD];   // layer-1 output
// weight tiles in FRAGMENT-MAJOR layout, tf32-rounded:
// [layer][chunk][warp_n(4)][ks(16)][lane(32)][q(8)]
//   q = nf*2 + half;  element (n,k): n = warp_n*32 + nf*8 + lane/4,
//                                    k = ks*8 + half*4 + lane%4
__device__ __align__(16) float g_wt[2 * NCHUNK * CHF];

__device__ __forceinline__ float to_tf32(float x) {
    float r;
    asm("cvt.rna.tf32.f32 %0, %1;" : "=f"(r) : "f"(x));
    return r;
}

// ---------------- preprocessing kernels ----------------
__global__ void count_kernel(const int* __restrict__ ei, const int* __restrict__ et, int E) {
    int e = blockIdx.x * blockDim.x + threadIdx.x;
    if (e < E) {
        int d = ei[E + e];
        int t = et[e];
        atomicAdd(&g_cnt[t * DN + d], 1);
    }
}

__global__ __launch_bounds__(1024) void scan_kernel(int E) {
    __shared__ int s[1024];
    __shared__ int sh_carry;
    __shared__ int sh_ex;
    const int tid = threadIdx.x;
    const int b   = blockIdx.x;
    if (tid == 0) sh_carry = 0;
    __syncthreads();
    const int base = b * SPAN;

    #pragma unroll
    for (int t = 0; t < 3; t++) {
        int i = base + t * 1024 + tid;
        int v = (i < NR) ? g_cnt[i] : 0;
        s[tid] = v;
        __syncthreads();
        for (int off = 1; off < 1024; off <<= 1) {
            int x = (tid >= off) ? s[tid - off] : 0;
            __syncthreads();
            s[tid] += x;
            __syncthreads();
        }
        int incl = s[tid];
        if (i < NR) g_rowptr2[i] = sh_carry + incl - v;
        __syncthreads();
        if (tid == 1023) sh_carry += incl;
        __syncthreads();
    }
    int total = sh_carry;

    if (tid == 0) {
        g_scan_agg[b] = total;
        if (b == 0) { g_scan_pfx[0] = total; sh_ex = 0; }
        __threadfence();
        *(volatile int*)&g_scan_flag[b] = (b == 0) ? 2 : 1;
    }
    if (b > 0 && tid < 32) {
        int lane = tid;
        int ex = 0;
        int idx = b - 1;
        while (true) {
            int j = idx - lane;
            int f = 0;
            if (j >= 0) {
                do { f = *(volatile int*)&g_scan_flag[j]; } while (f == 0);
            }
            int v = 0;
            if (j >= 0)
                v = (f == 2) ? *(volatile int*)&g_scan_pfx[j]
                             : *(volatile int*)&g_scan_agg[j];
            unsigned m = __ballot_sync(FULLM, (j >= 0) && (f == 2));
            int lead = m ? (__ffs(m) - 1) : 32;
            int contrib = (j >= 0 && lane <= lead) ? v : 0;
            #pragma unroll
            for (int off = 16; off; off >>= 1)
                contrib += __shfl_down_sync(FULLM, contrib, off);
            contrib = __shfl_sync(FULLM, contrib, 0);
            ex += contrib;
            if (m) break;
            idx -= 32;
        }
        if (lane == 0) {
            sh_ex = ex;
            g_scan_pfx[b] = ex + total;
            __threadfence();
            *(volatile int*)&g_scan_flag[b] = 2;
        }
    }
    __syncthreads();
    int ex = sh_ex;
    #pragma unroll
    for (int t = 0; t < 3; t++) {
        int i = base + t * 1024 + tid;
        if (i < NR) {
            int val = g_rowptr2[i] + ex;
            g_rowptr2[i] = val;
            g_woff[i] = val;
        }
    }
    if (b == 0 && tid == 0) g_rowptr2[NR] = E;
}

// merged: scatter (blocks [0,EB)) + weight prep into fragment-major layout
__global__ void scatter_wprep_kernel(
    const int* __restrict__ ei, const int* __restrict__ et, int E, int EB,
    const float* __restrict__ W1, const float* __restrict__ r1,
    const float* __restrict__ W2, const float* __restrict__ r2)
{
    int b = blockIdx.x;
    if (b < EB) {
        int e = b * 256 + threadIdx.x;
        if (e < E) {
            int s = ei[e];
            int d = ei[E + e];
            int t = et[e];
            int seg = t * DN + d;
            int pos = atomicAdd(&g_woff[seg], 1);
            g_emeta[pos] = make_int2((int)((unsigned)s | ((unsigned)d << 16)), 0);
        }
    } else {
        int id = (b - EB) * 256 + threadIdx.x;
        const int total = 2 * NCHUNK * CHF;
        if (id < total) {
            int l    = id / (NCHUNK * CHF);
            int rem  = id % (NCHUNK * CHF);
            int ch   = rem / CHF;            // 0 = root, 1..8 = relations 0..7
            int pos  = rem % CHF;
            int wn   = pos >> 12;            // warp_n 0..3
            int pos2 = pos & 4095;
            int ks   = pos2 >> 8;            // 0..15
            int pos3 = pos2 & 255;
            int lane = pos3 >> 3;            // 0..31
            int q    = pos3 & 7;             // nf*2 + half
            int nf   = q >> 1;
            int half = q & 1;
            int n = wn * 32 + nf * 8 + (lane >> 2);
            int k = ks * 8 + half * 4 + (lane & 3);
            const float* W  = l ? W2 : W1;
            const float* rt = l ? r2 : r1;
            // B[n][k] = W[k][n] (so D = A @ W)
            float wv = (ch > 0) ? W[((size_t)(ch - 1) * DD + k) * DD + n]
                                : rt[(size_t)k * DD + n];
            g_wt[id] = to_tf32(wv);
        }
    }
}

__global__ void tail_kernel(const float* __restrict__ rel, float* __restrict__ out) {
    int i = blockIdx.x * blockDim.x + threadIdx.x;
    if (i < DR * DD) out[i] = rel[i];
    if (i < SB) g_scan_flag[i] = 0;
    for (int j = i; j < NR; j += gridDim.x * blockDim.x) g_cnt[j] = 0;
}

// ---------------- fused RGCN layer (MT=64, 3 CTA/SM, B frags via LDG) --------
__device__ __forceinline__ void mma_tf32(float c[4],
    uint32_t a0, uint32_t a1, uint32_t a2, uint32_t a3,
    uint32_t b0, uint32_t b1)
{
    asm volatile(
        "mma.sync.aligned.m16n8k8.row.col.f32.tf32.tf32.f32 "
        "{%0,%1,%2,%3}, {%4,%5,%6,%7}, {%8,%9}, {%0,%1,%2,%3};\n"
        : "+f"(c[0]), "+f"(c[1]), "+f"(c[2]), "+f"(c[3])
        : "r"(a0), "r"(a1), "r"(a2), "r"(a3), "r"(b0), "r"(b1));
}

__device__ __forceinline__ void ldsm4(uint32_t& r0, uint32_t& r1, uint32_t& r2, uint32_t& r3,
                                      uint32_t addr)
{
    asm volatile("ldmatrix.sync.aligned.m8n8.x4.shared.b16 {%0,%1,%2,%3}, [%4];"
                 : "=r"(r0), "=r"(r1), "=r"(r2), "=r"(r3) : "r"(addr));
}

#define MT    64   // M tile (nodes per CTA)
#define NT    256  // threads per CTA (8 warps)
#define PAD   132  // fp32 row stride
#define A_FLOATS (MT * PAD)
#define SMEM_BYTES (A_FLOATS * 4)   // 33,792 B -> 3 CTAs/SM (regs permitting)

__global__ __launch_bounds__(NT, 3) void fused_layer_kernel(
    const float* __restrict__ X,
    const float* __restrict__ WT,    // layer base of g_wt (fragment-major)
    const float* __restrict__ bias,
    float* __restrict__ out, int N)
{
    extern __shared__ char smem[];
    float* As = (float*)smem;               // MT x PAD

    const int tid  = threadIdx.x;
    const int w    = tid >> 5;              // 0..7
    const int lane = tid & 31;
    const int m0   = blockIdx.x * MT;
    const int warp_m = w >> 2;              // 0..1 (32 rows each)
    const int warp_n = w & 3;               // 0..3 (32 cols each)
    const int g = lane >> 2;
    const int t = lane & 3;
    const int w8 = w * 8;                   // this warp's 8 contiguous A rows

    float C[2][4][4];                       // 32 regs
    #pragma unroll
    for (int a = 0; a < 2; a++)
        #pragma unroll
        for (int b = 0; b < 4; b++)
            #pragma unroll
            for (int q = 0; q < 4; q++) C[a][b][q] = 0.0f;

    // ldmatrix lane addresses for A (shared-space, bytes)
    uint32_t As_u = (uint32_t)__cvta_generic_to_shared(As);
    uint32_t a_addr[2];
    #pragma unroll
    for (int mf = 0; mf < 2; mf++) {
        int r0m = warp_m * 32 + mf * 16;
        a_addr[mf] = As_u + (((r0m + (lane & 15)) * PAD) + ((lane >> 4) << 2)) * 4;
    }
    // per-lane B fragment base (fragment-major gmem)
    const float* BW = WT + warp_n * 4096 + lane * 8;

    for (int ch = 0; ch < NCHUNK; ch++) {
        // ---- build A tile (fp32); each warp owns 8 contiguous rows ----
        int rp = 0;
        if (ch > 0) {
            int rel = ch - 1;
            #pragma unroll
            for (int i = 0; i < 8; i++)
                *(float4*)(As + (w8 + i) * PAD + lane * 4) =
                    make_float4(0.f, 0.f, 0.f, 0.f);

            if (lane < 9) {
                int rr = m0 + w8 + lane;
                if (rr > N) rr = N;
                rp = g_rowptr2[rel * DN + rr];
            }
            int wbeg = __shfl_sync(FULLM, rp, 0);
            int wend = __shfl_sync(FULLM, rp, 8);

            for (int e0 = wbeg; e0 < wend; e0 += 32) {
                int idx = e0 + lane;
                int2 mt = make_int2(0, 0);
                if (idx < wend) mt = g_emeta[idx];
                int cnt = wend - e0; if (cnt > 32) cnt = 32;
                for (int j = 0; j < cnt; j += 8) {
                    int nb = cnt - j; if (nb > 8) nb = 8;
                    int pk[8]; float4 v[8];
                    #pragma unroll
                    for (int q = 0; q < 8; q++)
                        pk[q] = __shfl_sync(FULLM, mt.x, j + q);
                    #pragma unroll
                    for (int q = 0; q < 8; q++)
                        if (q < nb)
                            v[q] = *(const float4*)(X +
                                   (size_t)((unsigned)pk[q] & 0xffffu) * DD + lane * 4);
                    #pragma unroll
                    for (int q = 0; q < 8; q++)
                        if (q < nb) {
                            int dl = (int)(((unsigned)pk[q]) >> 16) - m0;
                            float* rpt = As + dl * PAD + lane * 4;
                            float4 cur = *(float4*)rpt;
                            cur.x += v[q].x;
                            cur.y += v[q].y;
                            cur.z += v[q].z;
                            cur.w += v[q].w;
                            *(float4*)rpt = cur;
                        }
                }
            }
            // scale by per-row coef (sum -> mean) + tf32-round, in place
            #pragma unroll
            for (int i = 0; i < 8; i++) {
                int b0 = __shfl_sync(FULLM, rp, i);
                int b1 = __shfl_sync(FULLM, rp, i + 1);
                int c  = b1 - b0;
                float coef = 1.0f / (float)(c > 0 ? c : 1);
                float* rpt = As + (w8 + i) * PAD + lane * 4;
                float4 vv = *(float4*)rpt;
                vv.x = to_tf32(vv.x * coef); vv.y = to_tf32(vv.y * coef);
                vv.z = to_tf32(vv.z * coef); vv.w = to_tf32(vv.w * coef);
                *(float4*)rpt = vv;
            }
        } else {
            // root chunk: A = X tile (tf32-rounded)
            #pragma unroll
            for (int i = 0; i < 8; i++) {
                int row  = w8 + i;
                int node = m0 + row;
                float4 v = make_float4(0.f, 0.f, 0.f, 0.f);
                if (node < N) v = *(const float4*)(X + (size_t)node * DD + lane * 4);
                v.x = to_tf32(v.x); v.y = to_tf32(v.y);
                v.z = to_tf32(v.z); v.w = to_tf32(v.w);
                *(float4*)(As + row * PAD + lane * 4) = v;
            }
        }
        __syncthreads();

        // ---- MMA: 16 k-steps of m16n8k8 tf32; B frags via 2x LDG.128 (L1-hot) ----
        const float* BF = BW + ch * CHF;
        #pragma unroll 4
        for (int ks = 0; ks < 16; ks++) {
            float4 u0 = *(const float4*)(BF + ks * 256);
            float4 u1 = *(const float4*)(BF + ks * 256 + 4);
            uint32_t koff = ks * 32;
            uint32_t af[2][4];
            #pragma unroll
            for (int mf = 0; mf < 2; mf++)
                ldsm4(af[mf][0], af[mf][1], af[mf][2], af[mf][3],
                      a_addr[mf] + koff);
            #pragma unroll
            for (int mf = 0; mf < 2; mf++) {
                mma_tf32(C[mf][0], af[mf][0], af[mf][1], af[mf][2], af[mf][3],
                         __float_as_uint(u0.x), __float_as_uint(u0.y));
                mma_tf32(C[mf][1], af[mf][0], af[mf][1], af[mf][2], af[mf][3],
                         __float_as_uint(u0.z), __float_as_uint(u0.w));
                mma_tf32(C[mf][2], af[mf][0], af[mf][1], af[mf][2], af[mf][3],
                         __float_as_uint(u1.x), __float_as_uint(u1.y));
                mma_tf32(C[mf][3], af[mf][0], af[mf][1], af[mf][2], af[mf][3],
                         __float_as_uint(u1.z), __float_as_uint(u1.w));
            }
        }
        __syncthreads();   // A frag reads done before next chunk's rewrite
    }

    // ---- epilogue: + bias, ReLU ----
    #pragma unroll
    for (int mf = 0; mf < 2; mf++)
        #pragma unroll
        for (int nf = 0; nf < 4; nf++) {
            int row = warp_m * 32 + mf * 16 + g;
            int col = warp_n * 32 + nf * 8 + 2 * t;
            float b0 = bias[col], b1 = bias[col + 1];
            int node0 = m0 + row;
            if (node0 < N) {
                float o0 = C[mf][nf][0] + b0; o0 = o0 > 0.f ? o0 : 0.f;
                float o1 = C[mf][nf][1] + b1; o1 = o1 > 0.f ? o1 : 0.f;
                *(float2*)(out + (size_t)node0 * DD + col) = make_float2(o0, o1);
            }
            int node1 = m0 + row + 8;
            if (node1 < N) {
                float o2 = C[mf][nf][2] + b0; o2 = o2 > 0.f ? o2 : 0.f;
                float o3 = C[mf][nf][3] + b1; o3 = o3 > 0.f ? o3 : 0.f;
                *(float2*)(out + (size_t)node1 * DD + col) = make_float2(o2, o3);
            }
        }
}

// ---------------- launch ----------------
extern "C" void kernel_launch(void* const* d_in, const int* in_sizes, int n_in,
                              void* d_out, int out_size) {
    const float* x     = (const float*)d_in[0];
    const int*   ei    = (const int*)d_in[1];
    const int*   et    = (const int*)d_in[2];
    const float* W1    = (const float*)d_in[3];
    const float* root1 = (const float*)d_in[4];
    const float* b1    = (const float*)d_in[5];
    const float* W2    = (const float*)d_in[6];
    const float* root2 = (const float*)d_in[7];
    const float* b2    = (const float*)d_in[8];
    const float* rel   = (const float*)d_in[9];

    const int N = in_sizes[0] / DD;   // 50000
    const int E = in_sizes[2];        // 600000

    float* h1;  cudaGetSymbolAddress((void**)&h1, g_h);
    float* wt;  cudaGetSymbolAddress((void**)&wt, g_wt);

    float* out_h   = (float*)d_out;
    float* out_rel = (float*)d_out + (size_t)N * DD;

    // ---- preprocessing: 3 launches ----
    count_kernel<<<(E + 255) / 256, 256>>>(ei, et, E);             // launch 1
    scan_kernel<<<SB, 1024>>>(E);                                  // launch 2
    const int EB = (E + 255) / 256;
    const int WB = (2 * NCHUNK * CHF + 255) / 256;
    scatter_wprep_kernel<<<EB + WB, 256>>>(ei, et, E, EB,
                                           W1, root1, W2, root2);  // launch 3

    const int grid = (N + MT - 1) / MT;   // 782

    // ---- layer 1 (launch 4 — ncu capture lands here) ----
    fused_layer_kernel<<<grid, NT, SMEM_BYTES>>>(x, wt, b1, h1, N);
    // ---- layer 2 ----
    fused_layer_kernel<<<grid, NT, SMEM_BYTES>>>(h1, wt + NCHUNK * CHF, b2, out_h, N);

    // ---- tail ----
    tail_kernel<<<400, 1024>>>(rel, out_rel);
}

// round 17
// speedup vs baseline: 1.8771x; 1.8771x over previous
#include <cuda_runtime.h>
#include <cuda_bf16.h>
#include <stdint.h>

// Problem constants (fixed by dataset)
#define DN 50000     // nodes
#define DE 600000    // edges
#define DD 128       // feature dim
#define DR 8         // relations
#define NR (DR * DN) // 400000 (rel,dst) segments, rel-major
#define NCHUNK 9     // root + 8 relations
#define FULLM 0xffffffffu
#define SB   131     // scan blocks (co-resident, spin-safe)
#define SPAN 3072
#define CHF  (DD * DD)   // 16384 floats per chunk weight tile

// ---------------- scratch (device globals; no allocs allowed) ----------------
__device__ int   g_cnt[NR];
__device__ int   g_rowptr2[NR + 1];
__device__ int   g_woff[NR];
__device__ int   g_scan_agg[SB];
__device__ int   g_scan_pfx[SB];
__device__ int   g_scan_flag[SB];
__device__ int   g_esrc[DE];             // per-edge src, CSR order (rel-major)
__device__ float g_h[(size_t)DN * DD];   // layer-1 output
// mean-aggregated feature matrix: [chunk][node][128]; chunk0 = tf32(X)
__device__ __align__(16) float g_m[(size_t)NCHUNK * DN * DD];
// weight tiles [layer][chunk][n][k] (B[n][k] = W[k][n]), tf32-rounded
__device__ __align__(16) float g_wt[2 * NCHUNK * CHF];

__device__ __forceinline__ float to_tf32(float x) {
    float r;
    asm("cvt.rna.tf32.f32 %0, %1;" : "=f"(r) : "f"(x));
    return r;
}

// ---------------- preprocessing kernels ----------------
__global__ void count_kernel(const int* __restrict__ ei, const int* __restrict__ et, int E) {
    int e = blockIdx.x * blockDim.x + threadIdx.x;
    if (e < E) {
        int d = ei[E + e];
        int t = et[e];
        atomicAdd(&g_cnt[t * DN + d], 1);
    }
}

__global__ __launch_bounds__(1024) void scan_kernel(int E) {
    __shared__ int s[1024];
    __shared__ int sh_carry;
    __shared__ int sh_ex;
    const int tid = threadIdx.x;
    const int b   = blockIdx.x;
    if (tid == 0) sh_carry = 0;
    __syncthreads();
    const int base = b * SPAN;

    #pragma unroll
    for (int t = 0; t < 3; t++) {
        int i = base + t * 1024 + tid;
        int v = (i < NR) ? g_cnt[i] : 0;
        s[tid] = v;
        __syncthreads();
        for (int off = 1; off < 1024; off <<= 1) {
            int x = (tid >= off) ? s[tid - off] : 0;
            __syncthreads();
            s[tid] += x;
            __syncthreads();
        }
        int incl = s[tid];
        if (i < NR) g_rowptr2[i] = sh_carry + incl - v;
        __syncthreads();
        if (tid == 1023) sh_carry += incl;
        __syncthreads();
    }
    int total = sh_carry;

    if (tid == 0) {
        g_scan_agg[b] = total;
        if (b == 0) { g_scan_pfx[0] = total; sh_ex = 0; }
        __threadfence();
        *(volatile int*)&g_scan_flag[b] = (b == 0) ? 2 : 1;
    }
    if (b > 0 && tid < 32) {
        int lane = tid;
        int ex = 0;
        int idx = b - 1;
        while (true) {
            int j = idx - lane;
            int f = 0;
            if (j >= 0) {
                do { f = *(volatile int*)&g_scan_flag[j]; } while (f == 0);
            }
            int v = 0;
            if (j >= 0)
                v = (f == 2) ? *(volatile int*)&g_scan_pfx[j]
                             : *(volatile int*)&g_scan_agg[j];
            unsigned m = __ballot_sync(FULLM, (j >= 0) && (f == 2));
            int lead = m ? (__ffs(m) - 1) : 32;
            int contrib = (j >= 0 && lane <= lead) ? v : 0;
            #pragma unroll
            for (int off = 16; off; off >>= 1)
                contrib += __shfl_down_sync(FULLM, contrib, off);
            contrib = __shfl_sync(FULLM, contrib, 0);
            ex += contrib;
            if (m) break;
            idx -= 32;
        }
        if (lane == 0) {
            sh_ex = ex;
            g_scan_pfx[b] = ex + total;
            __threadfence();
            *(volatile int*)&g_scan_flag[b] = 2;
        }
    }
    __syncthreads();
    int ex = sh_ex;
    #pragma unroll
    for (int t = 0; t < 3; t++) {
        int i = base + t * 1024 + tid;
        if (i < NR) {
            int val = g_rowptr2[i] + ex;
            g_rowptr2[i] = val;
            g_woff[i] = val;
        }
    }
    if (b == 0 && tid == 0) g_rowptr2[NR] = E;
}

// merged: scatter (blocks [0,EB)) + weight prep (blocks [EB, EB+WB))
__global__ void scatter_wprep_kernel(
    const int* __restrict__ ei, const int* __restrict__ et, int E, int EB,
    const float* __restrict__ W1, const float* __restrict__ r1,
    const float* __restrict__ W2, const float* __restrict__ r2)
{
    int b = blockIdx.x;
    if (b < EB) {
        int e = b * 256 + threadIdx.x;
        if (e < E) {
            int s = ei[e];
            int d = ei[E + e];
            int t = et[e];
            int seg = t * DN + d;
            int pos = atomicAdd(&g_woff[seg], 1);
            g_esrc[pos] = s;
        }
    } else {
        int id = (b - EB) * 256 + threadIdx.x;
        const int total = 2 * NCHUNK * CHF;
        if (id < total) {
            int l   = id / (NCHUNK * CHF);
            int rem = id % (NCHUNK * CHF);
            int ch  = rem / CHF;            // 0 = root, 1..8 = relations 0..7
            int pos = rem % CHF;
            int n = pos >> 7, k = pos & 127;
            const float* W  = l ? W2 : W1;
            const float* rt = l ? r2 : r1;
            // B[n][k] = W[k][n] (so D = A @ W)
            float wv = (ch > 0) ? W[((size_t)(ch - 1) * DD + k) * DD + n]
                                : rt[(size_t)k * DD + n];
            g_wt[id] = to_tf32(wv);
        }
    }
}

__global__ void tail_kernel(const float* __restrict__ rel, float* __restrict__ out) {
    int i = blockIdx.x * blockDim.x + threadIdx.x;
    if (i < DR * DD) out[i] = rel[i];
    if (i < SB) g_scan_flag[i] = 0;
    for (int j = i; j < NR; j += gridDim.x * blockDim.x) g_cnt[j] = 0;
}

// ---------------- gather: warp per (chunk,node); writes g_m ----------------
// warp id gw: gw < DN -> root copy (chunk 0); else seg = gw - DN (rel-major),
// and M row index == gw (layout [ch][n][128] with ch = rel+1).
__global__ __launch_bounds__(256) void gather_kernel(const float* __restrict__ X, int N) {
    int gw   = (blockIdx.x * 256 + threadIdx.x) >> 5;
    int lane = threadIdx.x & 31;
    if (gw >= NCHUNK * DN) return;

    float4 acc;
    if (gw < DN) {
        // root: tf32(X)
        float4 v = *(const float4*)(X + (size_t)gw * DD + lane * 4);
        acc = v;
        acc.x = to_tf32(acc.x); acc.y = to_tf32(acc.y);
        acc.z = to_tf32(acc.z); acc.w = to_tf32(acc.w);
    } else {
        int seg = gw - DN;
        int beg = g_rowptr2[seg];
        int end = g_rowptr2[seg + 1];
        acc = make_float4(0.f, 0.f, 0.f, 0.f);
        int e = beg;
        for (; e + 1 < end; e += 2) {
            int s0 = g_esrc[e];
            int s1 = g_esrc[e + 1];
            float4 v0 = *(const float4*)(X + (size_t)s0 * DD + lane * 4);
            float4 v1 = *(const float4*)(X + (size_t)s1 * DD + lane * 4);
            acc.x += v0.x + v1.x; acc.y += v0.y + v1.y;
            acc.z += v0.z + v1.z; acc.w += v0.w + v1.w;
        }
        if (e < end) {
            int s0 = g_esrc[e];
            float4 v0 = *(const float4*)(X + (size_t)s0 * DD + lane * 4);
            acc.x += v0.x; acc.y += v0.y; acc.z += v0.z; acc.w += v0.w;
        }
        int c = end - beg;
        float coef = 1.0f / (float)(c > 0 ? c : 1);
        acc.x = to_tf32(acc.x * coef); acc.y = to_tf32(acc.y * coef);
        acc.z = to_tf32(acc.z * coef); acc.w = to_tf32(acc.w * coef);
    }
    *(float4*)(g_m + (size_t)gw * DD + lane * 4) = acc;
}

// ---------------- mm: 4-stage cp.async pipelined GEMM over K=1152 ----------
__device__ __forceinline__ void mma_tf32(float c[4],
    uint32_t a0, uint32_t a1, uint32_t a2, uint32_t a3,
    uint32_t b0, uint32_t b1)
{
    asm volatile(
        "mma.sync.aligned.m16n8k8.row.col.f32.tf32.tf32.f32 "
        "{%0,%1,%2,%3}, {%4,%5,%6,%7}, {%8,%9}, {%0,%1,%2,%3};\n"
        : "+f"(c[0]), "+f"(c[1]), "+f"(c[2]), "+f"(c[3])
        : "r"(a0), "r"(a1), "r"(a2), "r"(a3), "r"(b0), "r"(b1));
}

__device__ __forceinline__ void ldsm4(uint32_t& r0, uint32_t& r1, uint32_t& r2, uint32_t& r3,
                                      uint32_t addr)
{
    asm volatile("ldmatrix.sync.aligned.m8n8.x4.shared.b16 {%0,%1,%2,%3}, [%4];"
                 : "=r"(r0), "=r"(r1), "=r"(r2), "=r"(r3) : "r"(addr));
}

#define SPAD  36                      // subtile row stride in floats (32 + 4 pad)
#define BOFF  (128 * SPAD * 4)        // B offset within a stage (bytes)
#define STB   (2 * 128 * SPAD * 4)    // stage bytes = 36,864
#define NSTAGE 4
#define NSUB  36                      // 1152 / 32 K-subtiles
#define MM_SMEM (NSTAGE * STB)        // 147,456 B

__global__ __launch_bounds__(256) void mm_kernel(
    const float* __restrict__ Mn,    // g_m  [9][DN][128]
    const float* __restrict__ WT,    // layer base of g_wt [9][128][128]
    const float* __restrict__ bias,
    float* __restrict__ out, int N)
{
    extern __shared__ __align__(16) char smem[];
    uint32_t smem_u;
    asm("{ .reg .u64 t; cvta.to.shared.u64 t, %1; cvt.u32.u64 %0, t; }"
        : "=r"(smem_u) : "l"(smem));

    const int tid  = threadIdx.x;
    const int w    = tid >> 5;              // 0..7
    const int lane = tid & 31;
    const int m0   = blockIdx.x * 128;
    const int warp_m = w >> 1;              // 0..3 (32 rows each)
    const int warp_n = w & 1;               // 0..1 (64 cols each)
    const int g = lane >> 2;
    const int t = lane & 3;

    float C[2][8][4];
    #pragma unroll
    for (int a = 0; a < 2; a++)
        #pragma unroll
        for (int b = 0; b < 8; b++)
            #pragma unroll
            for (int q = 0; q < 4; q++) C[a][b][q] = 0.0f;

    // intra-stage ldsm lane offsets (bytes)
    uint32_t a_off[2];
    #pragma unroll
    for (int mf = 0; mf < 2; mf++) {
        int r0m = warp_m * 32 + mf * 16;
        a_off[mf] = (uint32_t)(((r0m + (lane & 15)) * SPAD + ((lane >> 4) << 2)) * 4);
    }
    uint32_t b_off[4];
    #pragma unroll
    for (int j = 0; j < 4; j++) {
        int n0 = warp_n * 64 + j * 16;
        b_off[j] = (uint32_t)(BOFF +
                   ((n0 + (lane & 7) + ((lane & 16) >> 1)) * SPAD + ((lane & 8) >> 1)) * 4);
    }

    // per-thread cp.async assignments: 4 chunks of 16B for A, 4 for B
    // flat = v*256+tid: row r = flat>>3, col c = (flat&7)*4 floats
    // issue subtile kt into stage st
    auto issue = [&](int st, int kt) {
        int ch = kt >> 2;
        int kk = (kt & 3) << 5;
        const float* Ag = Mn + (size_t)ch * DN * DD + kk;
        const float* Bg = WT + ch * CHF + kk;
        uint32_t base = smem_u + st * STB;
        #pragma unroll
        for (int v = 0; v < 4; v++) {
            int flat = v * 256 + tid;
            int r = flat >> 3;
            int c = (flat & 7) << 2;
            int row = m0 + r;
            int ok = (row < N) ? 16 : 0;
            if (!ok) row = N - 1;
            uint32_t da = base + (uint32_t)((r * SPAD + c) * 4);
            asm volatile("cp.async.cg.shared.global [%0], [%1], 16, %2;\n"
                         :: "r"(da), "l"(Ag + (size_t)row * DD + c), "r"(ok));
            uint32_t db = base + (uint32_t)BOFF + (uint32_t)((r * SPAD + c) * 4);
            asm volatile("cp.async.cg.shared.global [%0], [%1], 16;\n"
                         :: "r"(db), "l"(Bg + r * DD + c));
        }
    };

    // prologue: fill stages 0..2
    issue(0, 0); asm volatile("cp.async.commit_group;\n");
    issue(1, 1); asm volatile("cp.async.commit_group;\n");
    issue(2, 2); asm volatile("cp.async.commit_group;\n");

    for (int kt = 0; kt < NSUB; kt++) {
        asm volatile("cp.async.wait_group 2;\n" ::: "memory");
        __syncthreads();
        uint32_t base = smem_u + (kt & 3) * STB;

        #pragma unroll
        for (int ks = 0; ks < 4; ks++) {
            uint32_t koff = ks * 32;
            uint32_t bf[8][2];
            #pragma unroll
            for (int j = 0; j < 4; j++)
                ldsm4(bf[2*j][0], bf[2*j][1], bf[2*j+1][0], bf[2*j+1][1],
                      base + b_off[j] + koff);
            uint32_t af[2][4];
            #pragma unroll
            for (int mf = 0; mf < 2; mf++)
                ldsm4(af[mf][0], af[mf][1], af[mf][2], af[mf][3],
                      base + a_off[mf] + koff);
            #pragma unroll
            for (int mf = 0; mf < 2; mf++)
                #pragma unroll
                for (int nf = 0; nf < 8; nf++)
                    mma_tf32(C[mf][nf], af[mf][0], af[mf][1], af[mf][2], af[mf][3],
                             bf[nf][0], bf[nf][1]);
        }

        // refill the stage consumed at kt-1 ( (kt+3)&3 == (kt-1)&3 ), guarded
        // by this iteration's syncthreads (all warps finished mma kt-1).
        if (kt + 3 < NSUB) issue((kt + 3) & 3, kt + 3);
        asm volatile("cp.async.commit_group;\n");   // empty group when no issue
    }

    // ---- epilogue: + bias, ReLU ----
    #pragma unroll
    for (int mf = 0; mf < 2; mf++)
        #pragma unroll
        for (int nf = 0; nf < 8; nf++) {
            int row = warp_m * 32 + mf * 16 + g;
            int col = warp_n * 64 + nf * 8 + 2 * t;
            float b0 = bias[col], b1 = bias[col + 1];
            int node0 = m0 + row;
            if (node0 < N) {
                float o0 = C[mf][nf][0] + b0; o0 = o0 > 0.f ? o0 : 0.f;
                float o1 = C[mf][nf][1] + b1; o1 = o1 > 0.f ? o1 : 0.f;
                *(float2*)(out + (size_t)node0 * DD + col) = make_float2(o0, o1);
            }
            int node1 = m0 + row + 8;
            if (node1 < N) {
                float o2 = C[mf][nf][2] + b0; o2 = o2 > 0.f ? o2 : 0.f;
                float o3 = C[mf][nf][3] + b1; o3 = o3 > 0.f ? o3 : 0.f;
                *(float2*)(out + (size_t)node1 * DD + col) = make_float2(o2, o3);
            }
        }
}

// ---------------- launch ----------------
extern "C" void kernel_launch(void* const* d_in, const int* in_sizes, int n_in,
                              void* d_out, int out_size) {
    const float* x     = (const float*)d_in[0];
    const int*   ei    = (const int*)d_in[1];
    const int*   et    = (const int*)d_in[2];
    const float* W1    = (const float*)d_in[3];
    const float* root1 = (const float*)d_in[4];
    const float* b1    = (const float*)d_in[5];
    const float* W2    = (const float*)d_in[6];
    const float* root2 = (const float*)d_in[7];
    const float* b2    = (const float*)d_in[8];
    const float* rel   = (const float*)d_in[9];

    const int N = in_sizes[0] / DD;   // 50000
    const int E = in_sizes[2];        // 600000

    float* h1;  cudaGetSymbolAddress((void**)&h1, g_h);
    float* mn;  cudaGetSymbolAddress((void**)&mn, g_m);
    float* wt;  cudaGetSymbolAddress((void**)&wt, g_wt);

    float* out_h   = (float*)d_out;
    float* out_rel = (float*)d_out + (size_t)N * DD;

    static int smem_set = 0;
    if (!smem_set) {
        cudaFuncSetAttribute(mm_kernel,
                             cudaFuncAttributeMaxDynamicSharedMemorySize, MM_SMEM);
        smem_set = 1;
    }

    // ---- preprocessing: 3 launches ----
    count_kernel<<<(E + 255) / 256, 256>>>(ei, et, E);             // 1
    scan_kernel<<<SB, 1024>>>(E);                                  // 2
    const int EB = (E + 255) / 256;
    const int WB = (2 * NCHUNK * CHF + 255) / 256;
    scatter_wprep_kernel<<<EB + WB, 256>>>(ei, et, E, EB,
                                           W1, root1, W2, root2);  // 3

    const int ggrid = (NCHUNK * DN * 32 + 255) / 256;   // 56,250
    const int mgrid = (N + 127) / 128;                  // 391

    // ---- layer 1 ----
    gather_kernel<<<ggrid, 256>>>(x, N);                           // 4 (ncu lands here)
    mm_kernel<<<mgrid, 256, MM_SMEM>>>(mn, wt, b1, h1, N);         // 5
    // ---- layer 2 ----
    gather_kernel<<<ggrid, 256>>>(h1, N);                          // 6
    mm_kernel<<<mgrid, 256, MM_SMEM>>>(mn, wt + NCHUNK * CHF, b2, out_h, N); // 7

    // ---- tail ----
    tail_kernel<<<400, 1024>>>(rel, out_rel);
}